// round 5
// baseline (speedup 1.0000x reference)
#include <cuda_runtime.h>
#include <cuda_fp16.h>
#include <cstdint>
#include <math.h>

// ---------------------------------------------------------------------------
// Problem constants (Flux dual-stream attention block)
// ---------------------------------------------------------------------------
#define S_TXT   512
#define S_IMG   2048
#define S_TOT   2560
#define DMODEL  3072
#define NHEADS  24
#define DH      128
#define D3      9216

// ---------------------------------------------------------------------------
// Scratch (device globals -- allocation is forbidden)
// ---------------------------------------------------------------------------
__device__ float g_qkv    [(size_t)S_IMG * D3];
__device__ float g_eqkv   [(size_t)S_TXT * D3];
__device__ float g_q      [(size_t)S_TOT * DMODEL];
__device__ float g_k      [(size_t)S_TOT * DMODEL];
__device__ float g_v      [(size_t)S_TOT * DMODEL];
__device__ float g_vt     [(size_t)DMODEL * S_TOT];
__device__ float g_sc     [(size_t)NHEADS * S_TOT * S_TOT];
__device__ float g_attn   [(size_t)S_TOT * DMODEL];
__device__ float g_wt_qkv [(size_t)D3 * DMODEL];
__device__ float g_wt_aqkv[(size_t)D3 * DMODEL];
__device__ float g_wt_out [(size_t)DMODEL * DMODEL];
__device__ float g_wt_aout[(size_t)DMODEL * DMODEL];

// ---------------------------------------------------------------------------
// fp16 pack (round-to-nearest): word = {lo, hi}
// ---------------------------------------------------------------------------
__device__ __forceinline__ uint32_t packh2(float lo, float hi) {
    uint32_t r;
    asm("cvt.rn.f16x2.f32 %0, %1, %2;" : "=r"(r) : "f"(hi), "f"(lo));
    return r;
}

// ---------------------------------------------------------------------------
// fp16 mma.sync NT GEMM:  C[z][M,N] = A[z][M,K] @ B[z][N,K]^T (+ bias[n])
//
// Block 128x128, K-tile 32, 256 threads = 8 warps (2 M x 4 N), warp tile
// 64x32 via m16n8k16 mma tiles. SMEM tiles staged PRE-PERMUTED into mma
// fragment order (fp16), XOR-swizzled chunks to kill STS bank conflicts.
//
// A region: blocks (mt 0..7, ks 0..1) stride 132 words; chunk c'=c^((c>>3)&3),
//           word = c'*4 + rhi*2 + khi  (compute reads LDS.128 at chunk(lane))
// B region: base 2112; blocks (nt 0..15, ks 0..1) stride 68 words;
//           chunk c'=c^((c>>4)&1), word = c'*2 + khi (compute LDS.64)
// Stage = 4288 words; double buffered = 34304 B dynamic smem.
// grid = (N/128, M/128, batch)
// ---------------------------------------------------------------------------
#define STAGE_WORDS 4288
#define B_BASE      2112
#define GEMM_SMEM_BYTES (2 * STAGE_WORDS * 4)

__global__ __launch_bounds__(256)
void gemm_nt_mma(const float* __restrict__ A, const float* __restrict__ B,
                 const float* __restrict__ bias, float* __restrict__ C,
                 int K, int lda, int ldb, int ldc,
                 long long sA, long long sB, long long sC)
{
    extern __shared__ uint32_t sm[];
    const int tid    = threadIdx.x;
    const int lane   = tid & 31;
    const int wid    = tid >> 5;
    const int warp_m = wid >> 2;       // 0..1
    const int warp_n = wid & 3;        // 0..3
    const int bm     = blockIdx.y * 128;
    const int bn     = blockIdx.x * 128;

    A += (size_t)blockIdx.z * sA + (size_t)bm * lda;
    B += (size_t)blockIdx.z * sB + (size_t)bn * ldb;
    C += (size_t)blockIdx.z * sC;

    // ---- staging precompute: thread owns (row r, k-half ks) of A and B ----
    const int r   = tid >> 1;          // 0..127
    const int ksh = tid & 1;           // which k16 half of the 32-wide tile
    const float* Ap = A + (size_t)r * lda + ksh * 16;
    const float* Bp = B + (size_t)r * ldb + ksh * 16;

    int asw[4], bsw[4];
    {
        const int g   = r & 7;
        const int rhi = (r >> 3) & 1;
        const int mt  = r >> 4;
        const int ab  = (mt * 2 + ksh) * 132;
        const int nt  = r >> 3;
        const int nin = r & 7;
        const int bb  = B_BASE + (nt * 2 + ksh) * 68;
#pragma unroll
        for (int tg = 0; tg < 4; tg++) {
            int ca = g * 4 + tg;  ca ^= (ca >> 3) & 3;
            asw[tg] = ab + ca * 4 + rhi * 2;
            int cb = nin * 4 + tg; cb ^= (cb >> 4) & 1;
            bsw[tg] = bb + cb * 2;
        }
    }

    // compute-side chunk indices (same swizzle)
    int clA = lane ^ ((lane >> 3) & 3);
    int clB = lane ^ ((lane >> 4) & 1);

    float acc[4][4][4];
#pragma unroll
    for (int m = 0; m < 4; m++)
#pragma unroll
        for (int n = 0; n < 4; n++)
#pragma unroll
            for (int x = 0; x < 4; x++) acc[m][n][x] = 0.0f;

    uint32_t* buf0 = sm;
    uint32_t* buf1 = sm + STAGE_WORDS;
    const int T = K >> 5;

    // ---- prologue: stage k-tile 0 ----
    {
        float fa[16], fb[16];
#pragma unroll
        for (int i = 0; i < 4; i++) {
            *(float4*)&fa[i * 4] = *(const float4*)(Ap + i * 4);
            *(float4*)&fb[i * 4] = *(const float4*)(Bp + i * 4);
        }
        uint32_t wa[8], wb[8];
#pragma unroll
        for (int p = 0; p < 8; p++) {
            wa[p] = packh2(fa[2 * p], fa[2 * p + 1]);
            wb[p] = packh2(fb[2 * p], fb[2 * p + 1]);
        }
#pragma unroll
        for (int tg = 0; tg < 4; tg++) {
            *(uint2*)(buf0 + asw[tg]) = make_uint2(wa[tg], wa[tg + 4]);
            *(uint2*)(buf0 + bsw[tg]) = make_uint2(wb[tg], wb[tg + 4]);
        }
    }
    __syncthreads();

    for (int t = 0; t < T; t++) {
        uint32_t* cur = (t & 1) ? buf1 : buf0;
        uint32_t* nxt = (t & 1) ? buf0 : buf1;

        // prefetch next k-tile
        float4 ra[4], rb[4];
        const bool more = (t + 1) < T;
        if (more) {
            const size_t ko = (size_t)(t + 1) * 32;
#pragma unroll
            for (int i = 0; i < 4; i++) {
                ra[i] = *(const float4*)(Ap + ko + i * 4);
                rb[i] = *(const float4*)(Bp + ko + i * 4);
            }
        }

        // compute on current buffer
#pragma unroll
        for (int ks = 0; ks < 2; ks++) {
            uint4 af[4];
            uint2 bf[4];
#pragma unroll
            for (int m = 0; m < 4; m++)
                af[m] = *(const uint4*)(cur + ((warp_m * 4 + m) * 2 + ks) * 132 + clA * 4);
#pragma unroll
            for (int n = 0; n < 4; n++)
                bf[n] = *(const uint2*)(cur + B_BASE + ((warp_n * 4 + n) * 2 + ks) * 68 + clB * 2);
#pragma unroll
            for (int m = 0; m < 4; m++)
#pragma unroll
                for (int n = 0; n < 4; n++)
                    asm volatile(
                        "mma.sync.aligned.m16n8k16.row.col.f32.f16.f16.f32 "
                        "{%0,%1,%2,%3}, {%4,%5,%6,%7}, {%8,%9}, {%0,%1,%2,%3};"
                        : "+f"(acc[m][n][0]), "+f"(acc[m][n][1]),
                          "+f"(acc[m][n][2]), "+f"(acc[m][n][3])
                        : "r"(af[m].x), "r"(af[m].z), "r"(af[m].y), "r"(af[m].w),
                          "r"(bf[n].x), "r"(bf[n].y));
        }

        // stage next tile
        if (more) {
            uint32_t wa[8], wb[8];
#pragma unroll
            for (int i = 0; i < 4; i++) {
                wa[2 * i]     = packh2(ra[i].x, ra[i].y);
                wa[2 * i + 1] = packh2(ra[i].z, ra[i].w);
                wb[2 * i]     = packh2(rb[i].x, rb[i].y);
                wb[2 * i + 1] = packh2(rb[i].z, rb[i].w);
            }
#pragma unroll
            for (int tg = 0; tg < 4; tg++) {
                *(uint2*)(nxt + asw[tg]) = make_uint2(wa[tg], wa[tg + 4]);
                *(uint2*)(nxt + bsw[tg]) = make_uint2(wb[tg], wb[tg + 4]);
            }
        }
        __syncthreads();
    }

    // ---- epilogue: STG.64 per C fragment pair ----
    const int g  = lane >> 2;
    const int tg = lane & 3;
#pragma unroll
    for (int m = 0; m < 4; m++) {
        const int row0 = bm + warp_m * 64 + m * 16 + g;
#pragma unroll
        for (int n = 0; n < 4; n++) {
            const int col = bn + warp_n * 32 + n * 8 + tg * 2;
            float bx = 0.f, by = 0.f;
            if (bias) { bx = bias[col]; by = bias[col + 1]; }
            float2 lo = make_float2(acc[m][n][0] + bx, acc[m][n][1] + by);
            float2 hi = make_float2(acc[m][n][2] + bx, acc[m][n][3] + by);
            *(float2*)(C + (size_t)row0 * ldc + col)       = lo;
            *(float2*)(C + (size_t)(row0 + 8) * ldc + col) = hi;
        }
    }
}

// ---------------------------------------------------------------------------
// Tiled transpose: out[C,R] = in[R,C]^T   (R, C multiples of 32)
// ---------------------------------------------------------------------------
__global__ __launch_bounds__(256)
void transpose_k(const float* __restrict__ in, float* __restrict__ out, int R, int C)
{
    __shared__ float t[32][33];
    const int bx = blockIdx.x * 32;
    const int by = blockIdx.y * 32;
    const int tx = threadIdx.x & 31;
    const int ty = threadIdx.x >> 5;
#pragma unroll
    for (int j = 0; j < 32; j += 8)
        t[ty + j][tx] = in[(size_t)(by + ty + j) * C + bx + tx];
    __syncthreads();
#pragma unroll
    for (int j = 0; j < 32; j += 8)
        out[(size_t)(bx + ty + j) * R + by + tx] = t[tx][ty + j];
}

// ---------------------------------------------------------------------------
// Fused per-(token, head) RMSNorm + RoPE (softmax scale folded into q)
// ---------------------------------------------------------------------------
__device__ __forceinline__ float warp_sum(float v) {
#pragma unroll
    for (int o = 16; o > 0; o >>= 1) v += __shfl_xor_sync(0xffffffffu, v, o);
    return v;
}

__global__ __launch_bounds__(128)
void fuse_norm_rope(const float* __restrict__ qkv, const float* __restrict__ eqkv,
                    const int* __restrict__ ids,
                    const float* __restrict__ nq_w,  const float* __restrict__ nk_w,
                    const float* __restrict__ naq_w, const float* __restrict__ nak_w,
                    float* __restrict__ Q, float* __restrict__ Ko, float* __restrict__ V)
{
    const int s = blockIdx.x;
    const int h = blockIdx.y;
    const int d = threadIdx.x;

    const float* src;
    const float* qw;
    const float* kw;
    if (s < S_TXT) { src = eqkv + (size_t)s * D3;           qw = naq_w; kw = nak_w; }
    else           { src = qkv  + (size_t)(s - S_TXT) * D3; qw = nq_w;  kw = nk_w; }

    float qv = src[h * DH + d];
    float kv = src[DMODEL   + h * DH + d];
    float vv = src[2*DMODEL + h * DH + d];

    __shared__ float sq[4], sk[4];
    float wq = warp_sum(qv * qv);
    float wk = warp_sum(kv * kv);
    const int w = d >> 5;
    if ((d & 31) == 0) { sq[w] = wq; sk[w] = wk; }
    __syncthreads();
    float qsum = sq[0] + sq[1] + sq[2] + sq[3];
    float ksum = sk[0] + sk[1] + sk[2] + sk[3];
    float qn = qv * rsqrtf(qsum * (1.0f / DH) + 1e-5f) * qw[d];
    float kn = kv * rsqrtf(ksum * (1.0f / DH) + 1e-5f) * kw[d];

    const int p = d >> 1;
    int axis, base, dax;
    if      (p < 8)  { axis = 0; base = 0;  dax = 16; }
    else if (p < 36) { axis = 1; base = 8;  dax = 56; }
    else             { axis = 2; base = 36; dax = 56; }
    float e    = (2.0f * (float)(p - base)) / (float)dax;
    float freq = expf(-e * 9.210340371976184f);
    float pos  = (float)ids[s * 3 + axis];
    float ang  = pos * freq;
    float cs, sn;
    sincosf(ang, &sn, &cs);

    float q_other = __shfl_xor_sync(0xffffffffu, qn, 1);
    float k_other = __shfl_xor_sync(0xffffffffu, kn, 1);
    float qr, kr;
    if (d & 1) { qr = qn * cs + q_other * sn; kr = kn * cs + k_other * sn; }
    else       { qr = qn * cs - q_other * sn; kr = kn * cs - k_other * sn; }

    const size_t o = (size_t)s * DMODEL + h * DH + d;
    Q[o]  = qr * 0.08838834764831845f;   // fold 1/sqrt(Dh)
    Ko[o] = kr;
    V[o]  = vv;
}

// ---------------------------------------------------------------------------
// Row softmax over 2560-wide rows. grid = NHEADS*S_TOT, 256 threads.
// ---------------------------------------------------------------------------
__global__ __launch_bounds__(256)
void softmax_kernel(float* __restrict__ S)
{
    const size_t rowi = blockIdx.x;
    float* p = S + rowi * S_TOT;
    const int tid = threadIdx.x;

    __shared__ float redm[8];
    __shared__ float reds[8];

    float m = -1e30f;
    for (int i = tid; i < S_TOT; i += 256) m = fmaxf(m, p[i]);
#pragma unroll
    for (int o = 16; o > 0; o >>= 1) m = fmaxf(m, __shfl_xor_sync(0xffffffffu, m, o));
    if ((tid & 31) == 0) redm[tid >> 5] = m;
    __syncthreads();
    float bm = redm[0];
#pragma unroll
    for (int w = 1; w < 8; w++) bm = fmaxf(bm, redm[w]);

    float sum = 0.0f;
    for (int i = tid; i < S_TOT; i += 256) {
        float e = expf(p[i] - bm);
        p[i] = e;
        sum += e;
    }
    sum = warp_sum(sum);
    if ((tid & 31) == 0) reds[tid >> 5] = sum;
    __syncthreads();
    float bs = reds[0] + reds[1] + reds[2] + reds[3]
             + reds[4] + reds[5] + reds[6] + reds[7];
    float inv = 1.0f / bs;
    for (int i = tid; i < S_TOT; i += 256) p[i] *= inv;
}

// ---------------------------------------------------------------------------
// kernel_launch
// ---------------------------------------------------------------------------
extern "C" void kernel_launch(void* const* d_in, const int* in_sizes, int n_in,
                              void* d_out, int out_size)
{
    const float* hidden     = (const float*)d_in[0];
    const float* enc        = (const float*)d_in[1];
    const int*   ids        = (const int*)  d_in[2];
    const float* w_qkv      = (const float*)d_in[3];
    const float* w_add_qkv  = (const float*)d_in[4];
    const float* b_add_qkv  = (const float*)d_in[5];
    const float* w_out      = (const float*)d_in[6];
    const float* b_out      = (const float*)d_in[7];
    const float* w_add_out  = (const float*)d_in[8];
    const float* b_add_out  = (const float*)d_in[9];
    const float* norm_q_w   = (const float*)d_in[10];
    const float* norm_k_w   = (const float*)d_in[11];
    const float* norm_aq_w  = (const float*)d_in[12];
    const float* norm_ak_w  = (const float*)d_in[13];
    float* out = (float*)d_out;

    float *qkv, *eqkv, *q, *k, *v, *vt, *sc, *attn;
    float *wtq, *wtaq, *wto, *wtao;
    cudaGetSymbolAddress((void**)&qkv,  g_qkv);
    cudaGetSymbolAddress((void**)&eqkv, g_eqkv);
    cudaGetSymbolAddress((void**)&q,    g_q);
    cudaGetSymbolAddress((void**)&k,    g_k);
    cudaGetSymbolAddress((void**)&v,    g_v);
    cudaGetSymbolAddress((void**)&vt,   g_vt);
    cudaGetSymbolAddress((void**)&sc,   g_sc);
    cudaGetSymbolAddress((void**)&attn, g_attn);
    cudaGetSymbolAddress((void**)&wtq,  g_wt_qkv);
    cudaGetSymbolAddress((void**)&wtaq, g_wt_aqkv);
    cudaGetSymbolAddress((void**)&wto,  g_wt_out);
    cudaGetSymbolAddress((void**)&wtao, g_wt_aout);

    cudaFuncSetAttribute(gemm_nt_mma, cudaFuncAttributeMaxDynamicSharedMemorySize,
                         GEMM_SMEM_BYTES);

    // 0) transpose weights so every GEMM is NT (K-major on both sides)
    transpose_k<<<dim3(D3/32, DMODEL/32), 256>>>(w_qkv,     wtq,  DMODEL, D3);
    transpose_k<<<dim3(D3/32, DMODEL/32), 256>>>(w_add_qkv, wtaq, DMODEL, D3);
    transpose_k<<<dim3(DMODEL/32, DMODEL/32), 256>>>(w_out,     wto,  DMODEL, DMODEL);
    transpose_k<<<dim3(DMODEL/32, DMODEL/32), 256>>>(w_add_out, wtao, DMODEL, DMODEL);

    // 1) qkv = hidden @ w_qkv
    gemm_nt_mma<<<dim3(D3/128, S_IMG/128, 1), 256, GEMM_SMEM_BYTES>>>(
        hidden, wtq, nullptr, qkv, DMODEL, DMODEL, DMODEL, D3, 0, 0, 0);

    // 2) eqkv = enc @ w_add_qkv + b
    gemm_nt_mma<<<dim3(D3/128, S_TXT/128, 1), 256, GEMM_SMEM_BYTES>>>(
        enc, wtaq, b_add_qkv, eqkv, DMODEL, DMODEL, DMODEL, D3, 0, 0, 0);

    // 3) RMSNorm + RoPE (+q scale) -> q,k,v [S,3072]
    fuse_norm_rope<<<dim3(S_TOT, NHEADS), 128>>>(
        qkv, eqkv, ids, norm_q_w, norm_k_w, norm_aq_w, norm_ak_w, q, k, v);

    // 3b) vt = v^T  -> [3072, 2560] == [24][128][2560]
    transpose_k<<<dim3(DMODEL/32, S_TOT/32), 256>>>(v, vt, S_TOT, DMODEL);

    // 4) scores[h] = (q*scale) @ k^T   batch over heads
    gemm_nt_mma<<<dim3(S_TOT/128, S_TOT/128, NHEADS), 256, GEMM_SMEM_BYTES>>>(
        q, k, nullptr, sc, DH, DMODEL, DMODEL, S_TOT,
        (long long)DH, (long long)DH, (long long)S_TOT * S_TOT);

    // 5) softmax
    softmax_kernel<<<NHEADS * S_TOT, 256>>>(sc);

    // 6) attn[:,h*128:(h+1)*128] = P_h @ V_h
    gemm_nt_mma<<<dim3(1, S_TOT/128, NHEADS), 256, GEMM_SMEM_BYTES>>>(
        sc, vt, nullptr, attn, S_TOT, S_TOT, S_TOT, DMODEL,
        (long long)S_TOT * S_TOT, (long long)DH * S_TOT, (long long)DH);

    // 7) img_out = attn[512:] @ w_out + b_out
    gemm_nt_mma<<<dim3(DMODEL/128, S_IMG/128, 1), 256, GEMM_SMEM_BYTES>>>(
        attn + (size_t)S_TXT * DMODEL, wto, b_out, out,
        DMODEL, DMODEL, DMODEL, DMODEL, 0, 0, 0);

    // 8) enc_out = attn[:512] @ w_add_out + b_add_out
    gemm_nt_mma<<<dim3(DMODEL/128, S_TXT/128, 1), 256, GEMM_SMEM_BYTES>>>(
        attn, wtao, b_add_out, out + (size_t)S_IMG * DMODEL,
        DMODEL, DMODEL, DMODEL, DMODEL, 0, 0, 0);
}

// round 6
// speedup vs baseline: 2.2969x; 2.2969x over previous
#include <cuda_runtime.h>
#include <cuda_fp16.h>
#include <cstdint>
#include <math.h>

// ---------------------------------------------------------------------------
// Problem constants (Flux dual-stream attention block)
// ---------------------------------------------------------------------------
#define S_TXT   512
#define S_IMG   2048
#define S_TOT   2560
#define DMODEL  3072
#define NHEADS  24
#define DH      128
#define D3      9216

// ---------------------------------------------------------------------------
// Scratch (device globals -- allocation is forbidden)
// ---------------------------------------------------------------------------
__device__ float g_qkv [(size_t)S_IMG * D3];                  // fp32 GEMM1 out
__device__ float g_eqkv[(size_t)S_TXT * D3];                  // fp32 GEMM2 out
__device__ float g_sc  [(size_t)NHEADS * S_TOT * S_TOT];      // fp32 scores

__device__ __align__(256) __half g_hh   [(size_t)S_IMG * DMODEL];
__device__ __align__(256) __half g_eh   [(size_t)S_TXT * DMODEL];
__device__ __align__(256) __half g_qh   [(size_t)S_TOT * DMODEL];
__device__ __align__(256) __half g_kh   [(size_t)S_TOT * DMODEL];
__device__ __align__(256) __half g_vt   [(size_t)DMODEL * S_TOT];
__device__ __align__(256) __half g_p    [(size_t)NHEADS * S_TOT * S_TOT];
__device__ __align__(256) __half g_attnh[(size_t)S_TOT * DMODEL];
__device__ __align__(256) __half g_wtq  [(size_t)D3 * DMODEL];
__device__ __align__(256) __half g_wtaq [(size_t)D3 * DMODEL];
__device__ __align__(256) __half g_wto  [(size_t)DMODEL * DMODEL];
__device__ __align__(256) __half g_wtao [(size_t)DMODEL * DMODEL];

// ---------------------------------------------------------------------------
// helpers
// ---------------------------------------------------------------------------
__device__ __forceinline__ uint32_t smem_u32(const void* p) {
    uint32_t a;
    asm("{ .reg .u64 t; cvta.to.shared.u64 t, %1; cvt.u32.u64 %0, t; }" : "=r"(a) : "l"(p));
    return a;
}
__device__ __forceinline__ uint32_t packh2(float lo, float hi) {
    uint32_t r;
    asm("cvt.rn.f16x2.f32 %0, %1, %2;" : "=r"(r) : "f"(hi), "f"(lo));
    return r;
}
__device__ __forceinline__ void cp16(uint32_t saddr, const void* gptr) {
    asm volatile("cp.async.cg.shared.global [%0], [%1], 16;" :: "r"(saddr), "l"(gptr));
}
__device__ __forceinline__ void ldmx4(uint4& f, uint32_t addr) {
    asm volatile("ldmatrix.sync.aligned.m8n8.x4.shared.b16 {%0,%1,%2,%3}, [%4];"
                 : "=r"(f.x), "=r"(f.y), "=r"(f.z), "=r"(f.w) : "r"(addr));
}

// ---------------------------------------------------------------------------
// fp16 cp.async-pipelined NT GEMM: C[z][M,N] = A[z][M,K] @ B[z][N,K]^T (+bias)
// Block 128x128, k-tile 32, 256 threads = 8 warps (2Mx4N), warp tile 64x32.
// 4-stage cp.async pipeline; XOR-swizzled smem; ldmatrix.x4 fragments.
// Smem stage = 8KB A + 8KB B; element (r, kchunk kc of 16B):
//   off = r*64 + (kc ^ ((r>>1)&3))*16   (conflict-free STS and ldmatrix)
// grid = (N/128, M/128, batch). out_half: C is __half (packed h2 stores).
// ---------------------------------------------------------------------------
#define STAGE_BYTES 16384
#define GEMM_SMEM_BYTES (4 * STAGE_BYTES)

__global__ __launch_bounds__(256)
void gemm_nt_h(const __half* __restrict__ A, const __half* __restrict__ B,
               const float* __restrict__ bias, void* __restrict__ Cv,
               int K, int lda, int ldb, int ldc,
               long long sA, long long sB, long long sC, int out_half)
{
    extern __shared__ char smem[];
    const uint32_t sbase = smem_u32(smem);
    const int tid    = threadIdx.x;
    const int lane   = tid & 31;
    const int wid    = tid >> 5;
    const int warp_m = wid >> 2;
    const int warp_n = wid & 3;
    const int bm     = blockIdx.y * 128;
    const int bn     = blockIdx.x * 128;

    A += (size_t)blockIdx.z * sA + (size_t)bm * lda;
    B += (size_t)blockIdx.z * sB + (size_t)bn * ldb;

    // staging assignment: 2 chunks (16B) per thread per matrix
    uint32_t soff[2];
    size_t   goa[2], gob[2];
#pragma unroll
    for (int j = 0; j < 2; j++) {
        const int c  = tid + j * 256;
        const int r  = c >> 2;
        const int kc = c & 3;
        const int sw = kc ^ ((r >> 1) & 3);
        soff[j] = (uint32_t)(r * 64 + sw * 16);
        goa[j]  = (size_t)r * lda + kc * 8;
        gob[j]  = (size_t)r * ldb + kc * 8;
    }

    const int T = K >> 5;

    // prologue: stages 0..2
#pragma unroll
    for (int s = 0; s < 3; s++) {
        const uint32_t sa = sbase + s * STAGE_BYTES;
        if (s < T) {
#pragma unroll
            for (int j = 0; j < 2; j++) {
                cp16(sa + soff[j],        A + goa[j] + s * 32);
                cp16(sa + 8192 + soff[j], B + gob[j] + s * 32);
            }
        }
        asm volatile("cp.async.commit_group;");
    }

    float acc[4][4][4];
#pragma unroll
    for (int m = 0; m < 4; m++)
#pragma unroll
        for (int n = 0; n < 4; n++)
#pragma unroll
            for (int x = 0; x < 4; x++) acc[m][n][x] = 0.0f;

    // fragment address lane constants
    const int p    = lane >> 3;         // 0..3
    const int li   = lane & 7;
    const int rA0  = warp_m * 64 + (p & 1) * 8 + li;
    const int rB0  = warp_n * 32 + (p & 1) * 8 + li;
    const int kaddp = p >> 1;           // +0 / +1 k-chunk

    for (int t = 0; t < T; t++) {
        asm volatile("cp.async.wait_group 2;");
        __syncthreads();

        // issue stage t+3
        {
            const int kt = t + 3;
            const uint32_t sa = sbase + (kt & 3) * STAGE_BYTES;
            if (kt < T) {
#pragma unroll
                for (int j = 0; j < 2; j++) {
                    cp16(sa + soff[j],        A + goa[j] + (size_t)kt * 32);
                    cp16(sa + 8192 + soff[j], B + gob[j] + (size_t)kt * 32);
                }
            }
            asm volatile("cp.async.commit_group;");
        }

        const uint32_t st = sbase + (t & 3) * STAGE_BYTES;
#pragma unroll
        for (int ks = 0; ks < 2; ks++) {
            const int kc = ks * 2 + kaddp;
            uint4 af[4];
#pragma unroll
            for (int mt = 0; mt < 4; mt++) {
                const int row = rA0 + mt * 16;
                const int sw  = kc ^ ((row >> 1) & 3);
                ldmx4(af[mt], st + row * 64 + sw * 16);
            }
            uint4 bq[2];
#pragma unroll
            for (int ntp = 0; ntp < 2; ntp++) {
                const int row = rB0 + ntp * 16;
                const int sw  = kc ^ ((row >> 1) & 3);
                ldmx4(bq[ntp], st + 8192 + row * 64 + sw * 16);
            }
            uint2 bf[4];
            bf[0] = make_uint2(bq[0].x, bq[0].z);
            bf[1] = make_uint2(bq[0].y, bq[0].w);
            bf[2] = make_uint2(bq[1].x, bq[1].z);
            bf[3] = make_uint2(bq[1].y, bq[1].w);
#pragma unroll
            for (int m = 0; m < 4; m++)
#pragma unroll
                for (int n = 0; n < 4; n++)
                    asm volatile(
                        "mma.sync.aligned.m16n8k16.row.col.f32.f16.f16.f32 "
                        "{%0,%1,%2,%3}, {%4,%5,%6,%7}, {%8,%9}, {%0,%1,%2,%3};"
                        : "+f"(acc[m][n][0]), "+f"(acc[m][n][1]),
                          "+f"(acc[m][n][2]), "+f"(acc[m][n][3])
                        : "r"(af[m].x), "r"(af[m].y), "r"(af[m].z), "r"(af[m].w),
                          "r"(bf[n].x), "r"(bf[n].y));
        }
        __syncthreads();
    }

    // ---- epilogue ----
    const int g  = lane >> 2;
    const int tg = lane & 3;
    if (out_half) {
        __half* C = (__half*)Cv + (size_t)blockIdx.z * sC;
#pragma unroll
        for (int m = 0; m < 4; m++) {
            const int row0 = bm + warp_m * 64 + m * 16 + g;
#pragma unroll
            for (int n = 0; n < 4; n++) {
                const int col = bn + warp_n * 32 + n * 8 + tg * 2;
                *(uint32_t*)(C + (size_t)row0 * ldc + col) =
                    packh2(acc[m][n][0], acc[m][n][1]);
                *(uint32_t*)(C + (size_t)(row0 + 8) * ldc + col) =
                    packh2(acc[m][n][2], acc[m][n][3]);
            }
        }
    } else {
        float* C = (float*)Cv + (size_t)blockIdx.z * sC;
#pragma unroll
        for (int m = 0; m < 4; m++) {
            const int row0 = bm + warp_m * 64 + m * 16 + g;
#pragma unroll
            for (int n = 0; n < 4; n++) {
                const int col = bn + warp_n * 32 + n * 8 + tg * 2;
                float bx = 0.f, by = 0.f;
                if (bias) { bx = bias[col]; by = bias[col + 1]; }
                *(float2*)(C + (size_t)row0 * ldc + col) =
                    make_float2(acc[m][n][0] + bx, acc[m][n][1] + by);
                *(float2*)(C + (size_t)(row0 + 8) * ldc + col) =
                    make_float2(acc[m][n][2] + bx, acc[m][n][3] + by);
            }
        }
    }
}

// ---------------------------------------------------------------------------
// float -> half elementwise (n multiple of 1024)
// ---------------------------------------------------------------------------
__global__ __launch_bounds__(256)
void f2h_kernel(const float* __restrict__ in, __half* __restrict__ out)
{
    const size_t i = ((size_t)blockIdx.x * 256 + threadIdx.x) * 4;
    float4 v = *(const float4*)(in + i);
    *(uint2*)(out + i) = make_uint2(packh2(v.x, v.y), packh2(v.z, v.w));
}

// ---------------------------------------------------------------------------
// Tiled transpose fp32 -> fp16: out[C,R] = half(in[R,C]^T)
// ---------------------------------------------------------------------------
__global__ __launch_bounds__(256)
void transpose_h(const float* __restrict__ in, __half* __restrict__ out, int R, int C)
{
    __shared__ float t[32][33];
    const int bx = blockIdx.x * 32;
    const int by = blockIdx.y * 32;
    const int tx = threadIdx.x & 31;
    const int ty = threadIdx.x >> 5;
#pragma unroll
    for (int j = 0; j < 32; j += 8)
        t[ty + j][tx] = in[(size_t)(by + ty + j) * C + bx + tx];
    __syncthreads();
#pragma unroll
    for (int j = 0; j < 32; j += 8)
        out[(size_t)(bx + ty + j) * R + by + tx] = __float2half(t[tx][ty + j]);
}

// ---------------------------------------------------------------------------
// Fused RMSNorm + RoPE -> fp16 q,k (row-major) and fp16 V^T (scattered)
// ---------------------------------------------------------------------------
__device__ __forceinline__ float warp_sum(float v) {
#pragma unroll
    for (int o = 16; o > 0; o >>= 1) v += __shfl_xor_sync(0xffffffffu, v, o);
    return v;
}

__global__ __launch_bounds__(128)
void fuse_norm_rope(const float* __restrict__ qkv, const float* __restrict__ eqkv,
                    const int* __restrict__ ids,
                    const float* __restrict__ nq_w,  const float* __restrict__ nk_w,
                    const float* __restrict__ naq_w, const float* __restrict__ nak_w,
                    __half* __restrict__ Q, __half* __restrict__ Ko,
                    __half* __restrict__ VT)
{
    const int s = blockIdx.x;
    const int h = blockIdx.y;
    const int d = threadIdx.x;

    const float* src;
    const float* qw;
    const float* kw;
    if (s < S_TXT) { src = eqkv + (size_t)s * D3;           qw = naq_w; kw = nak_w; }
    else           { src = qkv  + (size_t)(s - S_TXT) * D3; qw = nq_w;  kw = nk_w; }

    float qv = src[h * DH + d];
    float kv = src[DMODEL   + h * DH + d];
    float vv = src[2*DMODEL + h * DH + d];

    __shared__ float sq[4], sk[4];
    float wq = warp_sum(qv * qv);
    float wk = warp_sum(kv * kv);
    const int w = d >> 5;
    if ((d & 31) == 0) { sq[w] = wq; sk[w] = wk; }
    __syncthreads();
    float qsum = sq[0] + sq[1] + sq[2] + sq[3];
    float ksum = sk[0] + sk[1] + sk[2] + sk[3];
    float qn = qv * rsqrtf(qsum * (1.0f / DH) + 1e-5f) * qw[d];
    float kn = kv * rsqrtf(ksum * (1.0f / DH) + 1e-5f) * kw[d];

    const int pr = d >> 1;
    int axis, base, dax;
    if      (pr < 8)  { axis = 0; base = 0;  dax = 16; }
    else if (pr < 36) { axis = 1; base = 8;  dax = 56; }
    else              { axis = 2; base = 36; dax = 56; }
    float e    = (2.0f * (float)(pr - base)) / (float)dax;
    float freq = expf(-e * 9.210340371976184f);
    float pos  = (float)ids[s * 3 + axis];
    float ang  = pos * freq;
    float cs, sn;
    sincosf(ang, &sn, &cs);

    float q_other = __shfl_xor_sync(0xffffffffu, qn, 1);
    float k_other = __shfl_xor_sync(0xffffffffu, kn, 1);
    float qr, kr;
    if (d & 1) { qr = qn * cs + q_other * sn; kr = kn * cs + k_other * sn; }
    else       { qr = qn * cs - q_other * sn; kr = kn * cs - k_other * sn; }

    const size_t o = (size_t)s * DMODEL + h * DH + d;
    Q[o]  = __float2half(qr * 0.08838834764831845f);
    Ko[o] = __float2half(kr);
    VT[(size_t)(h * DH + d) * S_TOT + s] = __float2half(vv);
}

// ---------------------------------------------------------------------------
// Row softmax: fp32 scores in, fp16 probs out. grid = NHEADS*S_TOT, 256 thr.
// ---------------------------------------------------------------------------
__global__ __launch_bounds__(256)
void softmax_kernel(const float* __restrict__ S, __half* __restrict__ P)
{
    const size_t rowi = blockIdx.x;
    const float* p = S + rowi * S_TOT;
    __half* po = P + rowi * S_TOT;
    const int tid = threadIdx.x;

    __shared__ float redm[8];
    __shared__ float reds[8];

    float m = -1e30f;
    float loc[10];
#pragma unroll
    for (int j = 0; j < 10; j++) {
        loc[j] = p[tid + j * 256];
        m = fmaxf(m, loc[j]);
    }
#pragma unroll
    for (int o = 16; o > 0; o >>= 1) m = fmaxf(m, __shfl_xor_sync(0xffffffffu, m, o));
    if ((tid & 31) == 0) redm[tid >> 5] = m;
    __syncthreads();
    float bm = redm[0];
#pragma unroll
    for (int w = 1; w < 8; w++) bm = fmaxf(bm, redm[w]);

    float sum = 0.0f;
#pragma unroll
    for (int j = 0; j < 10; j++) {
        loc[j] = expf(loc[j] - bm);
        sum += loc[j];
    }
    sum = warp_sum(sum);
    if ((tid & 31) == 0) reds[tid >> 5] = sum;
    __syncthreads();
    float bs = reds[0] + reds[1] + reds[2] + reds[3]
             + reds[4] + reds[5] + reds[6] + reds[7];
    float inv = 1.0f / bs;
#pragma unroll
    for (int j = 0; j < 10; j++)
        po[tid + j * 256] = __float2half(loc[j] * inv);
}

// ---------------------------------------------------------------------------
// kernel_launch
// ---------------------------------------------------------------------------
extern "C" void kernel_launch(void* const* d_in, const int* in_sizes, int n_in,
                              void* d_out, int out_size)
{
    const float* hidden     = (const float*)d_in[0];
    const float* enc        = (const float*)d_in[1];
    const int*   ids        = (const int*)  d_in[2];
    const float* w_qkv      = (const float*)d_in[3];
    const float* w_add_qkv  = (const float*)d_in[4];
    const float* b_add_qkv  = (const float*)d_in[5];
    const float* w_out      = (const float*)d_in[6];
    const float* b_out      = (const float*)d_in[7];
    const float* w_add_out  = (const float*)d_in[8];
    const float* b_add_out  = (const float*)d_in[9];
    const float* norm_q_w   = (const float*)d_in[10];
    const float* norm_k_w   = (const float*)d_in[11];
    const float* norm_aq_w  = (const float*)d_in[12];
    const float* norm_ak_w  = (const float*)d_in[13];
    float* out = (float*)d_out;

    float *qkv, *eqkv, *sc;
    __half *hh, *eh, *qh, *kh, *vt, *pp, *attnh, *wtq, *wtaq, *wto, *wtao;
    cudaGetSymbolAddress((void**)&qkv,   g_qkv);
    cudaGetSymbolAddress((void**)&eqkv,  g_eqkv);
    cudaGetSymbolAddress((void**)&sc,    g_sc);
    cudaGetSymbolAddress((void**)&hh,    g_hh);
    cudaGetSymbolAddress((void**)&eh,    g_eh);
    cudaGetSymbolAddress((void**)&qh,    g_qh);
    cudaGetSymbolAddress((void**)&kh,    g_kh);
    cudaGetSymbolAddress((void**)&vt,    g_vt);
    cudaGetSymbolAddress((void**)&pp,    g_p);
    cudaGetSymbolAddress((void**)&attnh, g_attnh);
    cudaGetSymbolAddress((void**)&wtq,   g_wtq);
    cudaGetSymbolAddress((void**)&wtaq,  g_wtaq);
    cudaGetSymbolAddress((void**)&wto,   g_wto);
    cudaGetSymbolAddress((void**)&wtao,  g_wtao);

    cudaFuncSetAttribute(gemm_nt_h, cudaFuncAttributeMaxDynamicSharedMemorySize,
                         GEMM_SMEM_BYTES);

    // 0) convert activations, transpose+convert weights (all fp16 K-major)
    f2h_kernel<<<(S_IMG * DMODEL) / 1024, 256>>>(hidden, hh);
    f2h_kernel<<<(S_TXT * DMODEL) / 1024, 256>>>(enc, eh);
    transpose_h<<<dim3(D3/32, DMODEL/32), 256>>>(w_qkv,     wtq,  DMODEL, D3);
    transpose_h<<<dim3(D3/32, DMODEL/32), 256>>>(w_add_qkv, wtaq, DMODEL, D3);
    transpose_h<<<dim3(DMODEL/32, DMODEL/32), 256>>>(w_out,     wto,  DMODEL, DMODEL);
    transpose_h<<<dim3(DMODEL/32, DMODEL/32), 256>>>(w_add_out, wtao, DMODEL, DMODEL);

    // 1) qkv = hidden @ w_qkv            (fp32 out)
    gemm_nt_h<<<dim3(D3/128, S_IMG/128, 1), 256, GEMM_SMEM_BYTES>>>(
        hh, wtq, nullptr, qkv, DMODEL, DMODEL, DMODEL, D3, 0, 0, 0, 0);

    // 2) eqkv = enc @ w_add_qkv + b      (fp32 out)
    gemm_nt_h<<<dim3(D3/128, S_TXT/128, 1), 256, GEMM_SMEM_BYTES>>>(
        eh, wtaq, b_add_qkv, eqkv, DMODEL, DMODEL, DMODEL, D3, 0, 0, 0, 0);

    // 3) RMSNorm + RoPE -> fp16 q,k and fp16 V^T
    fuse_norm_rope<<<dim3(S_TOT, NHEADS), 128>>>(
        qkv, eqkv, ids, norm_q_w, norm_k_w, norm_aq_w, norm_ak_w, qh, kh, vt);

    // 4) scores[h] = (q*scale) @ k^T     (fp32 out)
    gemm_nt_h<<<dim3(S_TOT/128, S_TOT/128, NHEADS), 256, GEMM_SMEM_BYTES>>>(
        qh, kh, nullptr, sc, DH, DMODEL, DMODEL, S_TOT,
        (long long)DH, (long long)DH, (long long)S_TOT * S_TOT, 0);

    // 5) softmax -> fp16 probs
    softmax_kernel<<<NHEADS * S_TOT, 256>>>(sc, pp);

    // 6) attn = P @ V (per head)         (fp16 out)
    gemm_nt_h<<<dim3(1, S_TOT/128, NHEADS), 256, GEMM_SMEM_BYTES>>>(
        pp, vt, nullptr, attnh, S_TOT, S_TOT, S_TOT, DMODEL,
        (long long)S_TOT * S_TOT, (long long)DH * S_TOT, (long long)DH, 1);

    // 7) img_out = attn[512:] @ w_out + b_out
    gemm_nt_h<<<dim3(DMODEL/128, S_IMG/128, 1), 256, GEMM_SMEM_BYTES>>>(
        attnh + (size_t)S_TXT * DMODEL, wto, b_out, out,
        DMODEL, DMODEL, DMODEL, DMODEL, 0, 0, 0, 0);

    // 8) enc_out = attn[:512] @ w_add_out + b_add_out
    gemm_nt_h<<<dim3(DMODEL/128, S_TXT/128, 1), 256, GEMM_SMEM_BYTES>>>(
        attnh, wtao, b_add_out, out + (size_t)S_IMG * DMODEL,
        DMODEL, DMODEL, DMODEL, DMODEL, 0, 0, 0, 0);
}

// round 7
// speedup vs baseline: 2.6748x; 1.1645x over previous
#include <cuda_runtime.h>
#include <cuda_fp16.h>
#include <cstdint>
#include <math.h>

// ---------------------------------------------------------------------------
// Problem constants (Flux dual-stream attention block)
// ---------------------------------------------------------------------------
#define S_TXT   512
#define S_IMG   2048
#define S_TOT   2560
#define DMODEL  3072
#define NHEADS  24
#define DH      128
#define D3      9216

// ---------------------------------------------------------------------------
// Scratch (device globals -- allocation is forbidden)
// ---------------------------------------------------------------------------
__device__ float g_qkv [(size_t)S_IMG * D3];
__device__ float g_eqkv[(size_t)S_TXT * D3];

__device__ __align__(256) __half g_hh   [(size_t)S_IMG * DMODEL];
__device__ __align__(256) __half g_eh   [(size_t)S_TXT * DMODEL];
__device__ __align__(256) __half g_qh   [(size_t)S_TOT * DMODEL];
__device__ __align__(256) __half g_kh   [(size_t)S_TOT * DMODEL];
__device__ __align__(256) __half g_vt   [(size_t)DMODEL * S_TOT];
__device__ __align__(256) __half g_attnh[(size_t)S_TOT * DMODEL];
__device__ __align__(256) __half g_wtq  [(size_t)D3 * DMODEL];
__device__ __align__(256) __half g_wtaq [(size_t)D3 * DMODEL];
__device__ __align__(256) __half g_wto  [(size_t)DMODEL * DMODEL];
__device__ __align__(256) __half g_wtao [(size_t)DMODEL * DMODEL];

// ---------------------------------------------------------------------------
// helpers
// ---------------------------------------------------------------------------
__device__ __forceinline__ uint32_t smem_u32(const void* p) {
    uint32_t a;
    asm("{ .reg .u64 t; cvta.to.shared.u64 t, %1; cvt.u32.u64 %0, t; }" : "=r"(a) : "l"(p));
    return a;
}
__device__ __forceinline__ uint32_t packh2(float lo, float hi) {
    uint32_t r;
    asm("cvt.rn.f16x2.f32 %0, %1, %2;" : "=r"(r) : "f"(hi), "f"(lo));
    return r;
}
__device__ __forceinline__ void cp16(uint32_t saddr, const void* gptr) {
    asm volatile("cp.async.cg.shared.global [%0], [%1], 16;" :: "r"(saddr), "l"(gptr));
}
__device__ __forceinline__ void ldmx4(uint4& f, uint32_t addr) {
    asm volatile("ldmatrix.sync.aligned.m8n8.x4.shared.b16 {%0,%1,%2,%3}, [%4];"
                 : "=r"(f.x), "=r"(f.y), "=r"(f.z), "=r"(f.w) : "r"(addr));
}
#define MMA16816(acc, a, b0, b1)                                               \
    asm volatile("mma.sync.aligned.m16n8k16.row.col.f32.f16.f16.f32 "          \
                 "{%0,%1,%2,%3}, {%4,%5,%6,%7}, {%8,%9}, {%0,%1,%2,%3};"       \
                 : "+f"((acc)[0]), "+f"((acc)[1]), "+f"((acc)[2]), "+f"((acc)[3]) \
                 : "r"((a).x), "r"((a).y), "r"((a).z), "r"((a).w),             \
                   "r"(b0), "r"(b1))

// ---------------------------------------------------------------------------
// fp16 cp.async-pipelined NT GEMM (unchanged from R6; proven)
// ---------------------------------------------------------------------------
#define STAGE_BYTES 16384
#define GEMM_SMEM_BYTES (4 * STAGE_BYTES)

__global__ __launch_bounds__(256)
void gemm_nt_h(const __half* __restrict__ A, const __half* __restrict__ B,
               const float* __restrict__ bias, void* __restrict__ Cv,
               int K, int lda, int ldb, int ldc,
               long long sA, long long sB, long long sC, int out_half)
{
    extern __shared__ char smem[];
    const uint32_t sbase = smem_u32(smem);
    const int tid    = threadIdx.x;
    const int lane   = tid & 31;
    const int wid    = tid >> 5;
    const int warp_m = wid >> 2;
    const int warp_n = wid & 3;
    const int bm     = blockIdx.y * 128;
    const int bn     = blockIdx.x * 128;

    A += (size_t)blockIdx.z * sA + (size_t)bm * lda;
    B += (size_t)blockIdx.z * sB + (size_t)bn * ldb;

    uint32_t soff[2];
    size_t   goa[2], gob[2];
#pragma unroll
    for (int j = 0; j < 2; j++) {
        const int c  = tid + j * 256;
        const int r  = c >> 2;
        const int kc = c & 3;
        const int sw = kc ^ ((r >> 1) & 3);
        soff[j] = (uint32_t)(r * 64 + sw * 16);
        goa[j]  = (size_t)r * lda + kc * 8;
        gob[j]  = (size_t)r * ldb + kc * 8;
    }

    const int T = K >> 5;

#pragma unroll
    for (int s = 0; s < 3; s++) {
        const uint32_t sa = sbase + s * STAGE_BYTES;
        if (s < T) {
#pragma unroll
            for (int j = 0; j < 2; j++) {
                cp16(sa + soff[j],        A + goa[j] + s * 32);
                cp16(sa + 8192 + soff[j], B + gob[j] + s * 32);
            }
        }
        asm volatile("cp.async.commit_group;");
    }

    float acc[4][4][4];
#pragma unroll
    for (int m = 0; m < 4; m++)
#pragma unroll
        for (int n = 0; n < 4; n++)
#pragma unroll
            for (int x = 0; x < 4; x++) acc[m][n][x] = 0.0f;

    const int p    = lane >> 3;
    const int li   = lane & 7;
    const int rA0  = warp_m * 64 + (p & 1) * 8 + li;
    const int rB0  = warp_n * 32 + (p & 1) * 8 + li;
    const int kaddp = p >> 1;

    for (int t = 0; t < T; t++) {
        asm volatile("cp.async.wait_group 2;");
        __syncthreads();
        {
            const int kt = t + 3;
            const uint32_t sa = sbase + (kt & 3) * STAGE_BYTES;
            if (kt < T) {
#pragma unroll
                for (int j = 0; j < 2; j++) {
                    cp16(sa + soff[j],        A + goa[j] + (size_t)kt * 32);
                    cp16(sa + 8192 + soff[j], B + gob[j] + (size_t)kt * 32);
                }
            }
            asm volatile("cp.async.commit_group;");
        }

        const uint32_t st = sbase + (t & 3) * STAGE_BYTES;
#pragma unroll
        for (int ks = 0; ks < 2; ks++) {
            const int kc = ks * 2 + kaddp;
            uint4 af[4];
#pragma unroll
            for (int mt = 0; mt < 4; mt++) {
                const int row = rA0 + mt * 16;
                const int sw  = kc ^ ((row >> 1) & 3);
                ldmx4(af[mt], st + row * 64 + sw * 16);
            }
            uint4 bq[2];
#pragma unroll
            for (int ntp = 0; ntp < 2; ntp++) {
                const int row = rB0 + ntp * 16;
                const int sw  = kc ^ ((row >> 1) & 3);
                ldmx4(bq[ntp], st + 8192 + row * 64 + sw * 16);
            }
            uint2 bf[4];
            bf[0] = make_uint2(bq[0].x, bq[0].z);
            bf[1] = make_uint2(bq[0].y, bq[0].w);
            bf[2] = make_uint2(bq[1].x, bq[1].z);
            bf[3] = make_uint2(bq[1].y, bq[1].w);
#pragma unroll
            for (int m = 0; m < 4; m++)
#pragma unroll
                for (int n = 0; n < 4; n++)
                    MMA16816(acc[m][n], af[m], bf[n].x, bf[n].y);
        }
        __syncthreads();
    }

    const int g  = lane >> 2;
    const int tg = lane & 3;
    if (out_half) {
        __half* C = (__half*)Cv + (size_t)blockIdx.z * sC;
#pragma unroll
        for (int m = 0; m < 4; m++) {
            const int row0 = bm + warp_m * 64 + m * 16 + g;
#pragma unroll
            for (int n = 0; n < 4; n++) {
                const int col = bn + warp_n * 32 + n * 8 + tg * 2;
                *(uint32_t*)(C + (size_t)row0 * ldc + col) =
                    packh2(acc[m][n][0], acc[m][n][1]);
                *(uint32_t*)(C + (size_t)(row0 + 8) * ldc + col) =
                    packh2(acc[m][n][2], acc[m][n][3]);
            }
        }
    } else {
        float* C = (float*)Cv + (size_t)blockIdx.z * sC;
#pragma unroll
        for (int m = 0; m < 4; m++) {
            const int row0 = bm + warp_m * 64 + m * 16 + g;
#pragma unroll
            for (int n = 0; n < 4; n++) {
                const int col = bn + warp_n * 32 + n * 8 + tg * 2;
                float bx = 0.f, by = 0.f;
                if (bias) { bx = bias[col]; by = bias[col + 1]; }
                *(float2*)(C + (size_t)row0 * ldc + col) =
                    make_float2(acc[m][n][0] + bx, acc[m][n][1] + by);
                *(float2*)(C + (size_t)(row0 + 8) * ldc + col) =
                    make_float2(acc[m][n][2] + bx, acc[m][n][3] + by);
            }
        }
    }
}

// ---------------------------------------------------------------------------
// Fused flash attention: per CTA = (q-block 128, head). 256 thr = 8 warps,
// warp tile = 16 q-rows x 128 (kv or dh). Online softmax in registers.
// smem: Q 32KB | KV double buffer 2 x (K 32KB + V 32KB) = 160KB.
// Section layout (8KB, 128 rows x 64B): off = r*64 + (kc ^ ((r>>1)&3))*16.
// ---------------------------------------------------------------------------
#define FA_QSM   32768
#define FA_KV    65536
#define FA_SMEM  (FA_QSM + 2 * FA_KV)
#define NBLK     (S_TOT / 128)     // 20

__global__ __launch_bounds__(256)
void flash_attn(const __half* __restrict__ Qg, const __half* __restrict__ Kg,
                const __half* __restrict__ VTg, __half* __restrict__ Og)
{
    extern __shared__ char smem[];
    const uint32_t sbase = smem_u32(smem);
    const int tid  = threadIdx.x;
    const int lane = tid & 31;
    const int wid  = tid >> 5;
    const int qb   = blockIdx.x;
    const int h    = blockIdx.y;

    // staging: 2 x 16B chunks per thread per 8KB section
    uint32_t soff[2];
    int rr[2], kc8[2];
#pragma unroll
    for (int j = 0; j < 2; j++) {
        const int c  = tid + j * 256;
        const int r  = c >> 2;
        const int kc = c & 3;
        soff[j] = (uint32_t)(r * 64 + (kc ^ ((r >> 1) & 3)) * 16);
        rr[j]   = r;
        kc8[j]  = kc * 8;
    }

    const __half* Qp = Qg + (size_t)(qb * 128) * DMODEL + h * DH;
    const __half* Kp = Kg + h * DH;
    const __half* Vp = VTg + (size_t)(h * DH) * S_TOT;

    // issue Q (4 sections) + KV block 0  -> group 0
#pragma unroll
    for (int sec = 0; sec < 4; sec++)
#pragma unroll
        for (int j = 0; j < 2; j++)
            cp16(sbase + sec * 8192 + soff[j],
                 Qp + (size_t)rr[j] * DMODEL + sec * 32 + kc8[j]);
    {
        const uint32_t kb = sbase + FA_QSM;
#pragma unroll
        for (int sec = 0; sec < 4; sec++)
#pragma unroll
            for (int j = 0; j < 2; j++) {
                cp16(kb + sec * 8192 + soff[j],
                     Kp + (size_t)rr[j] * DMODEL + sec * 32 + kc8[j]);
                cp16(kb + 32768 + sec * 8192 + soff[j],
                     Vp + (size_t)rr[j] * S_TOT + sec * 32 + kc8[j]);
            }
    }
    asm volatile("cp.async.commit_group;");
    // KV block 1 -> group 1
    {
        const uint32_t kb = sbase + FA_QSM + FA_KV;
#pragma unroll
        for (int sec = 0; sec < 4; sec++)
#pragma unroll
            for (int j = 0; j < 2; j++) {
                cp16(kb + sec * 8192 + soff[j],
                     Kp + (size_t)(128 + rr[j]) * DMODEL + sec * 32 + kc8[j]);
                cp16(kb + 32768 + sec * 8192 + soff[j],
                     Vp + (size_t)rr[j] * S_TOT + 128 + sec * 32 + kc8[j]);
            }
    }
    asm volatile("cp.async.commit_group;");

    // lane constants
    const int p     = lane >> 3;
    const int li    = lane & 7;
    const int kaddp = p >> 1;
    const int rowQ  = wid * 16 + (p & 1) * 8 + li;
    const int rB0   = (p & 1) * 8 + li;
    const int g     = lane >> 2;
    const int tg    = lane & 3;

    float mrow[2] = {-1e30f, -1e30f};
    float lrow[2] = {0.f, 0.f};
    float o[16][4];
#pragma unroll
    for (int j = 0; j < 16; j++)
#pragma unroll
        for (int x = 0; x < 4; x++) o[j][x] = 0.f;
    uint4 qf[8];

    for (int jb = 0; jb < NBLK; jb++) {
        asm volatile("cp.async.wait_group 1;");
        __syncthreads();

        if (jb == 0) {
#pragma unroll
            for (int kc = 0; kc < 8; kc++) {
                const int sec = kc >> 1;
                const int c   = (kc & 1) * 2 + kaddp;
                const int sw  = c ^ ((rowQ >> 1) & 3);
                ldmx4(qf[kc], sbase + sec * 8192 + rowQ * 64 + sw * 16);
            }
        }

        const uint32_t kb = sbase + FA_QSM + (jb & 1) * FA_KV;
        const uint32_t vb = kb + 32768;

        // ---- S = Q @ K^T ----
        float sacc[16][4];
#pragma unroll
        for (int j = 0; j < 16; j++)
#pragma unroll
            for (int x = 0; x < 4; x++) sacc[j][x] = 0.f;
#pragma unroll
        for (int kc = 0; kc < 8; kc++) {
            const int sec = kc >> 1;
            const int c   = (kc & 1) * 2 + kaddp;
#pragma unroll
            for (int np = 0; np < 8; np++) {
                const int row = np * 16 + rB0;
                const int sw  = c ^ ((row >> 1) & 3);
                uint4 bq;
                ldmx4(bq, kb + sec * 8192 + row * 64 + sw * 16);
                MMA16816(sacc[np * 2],     qf[kc], bq.x, bq.z);
                MMA16816(sacc[np * 2 + 1], qf[kc], bq.y, bq.w);
            }
        }

        // ---- online softmax ----
        float mx0 = -1e30f, mx1 = -1e30f;
#pragma unroll
        for (int j = 0; j < 16; j++) {
            mx0 = fmaxf(mx0, fmaxf(sacc[j][0], sacc[j][1]));
            mx1 = fmaxf(mx1, fmaxf(sacc[j][2], sacc[j][3]));
        }
        mx0 = fmaxf(mx0, __shfl_xor_sync(0xffffffffu, mx0, 1));
        mx0 = fmaxf(mx0, __shfl_xor_sync(0xffffffffu, mx0, 2));
        mx1 = fmaxf(mx1, __shfl_xor_sync(0xffffffffu, mx1, 1));
        mx1 = fmaxf(mx1, __shfl_xor_sync(0xffffffffu, mx1, 2));

        const float mn0 = fmaxf(mrow[0], mx0);
        const float mn1 = fmaxf(mrow[1], mx1);
        const float sc0 = __expf(mrow[0] - mn0);
        const float sc1 = __expf(mrow[1] - mn1);
        mrow[0] = mn0; mrow[1] = mn1;

        float s0 = 0.f, s1 = 0.f;
        uint32_t pf[16][2];
#pragma unroll
        for (int j = 0; j < 16; j++) {
            const float e0 = __expf(sacc[j][0] - mn0);
            const float e1 = __expf(sacc[j][1] - mn0);
            const float e2 = __expf(sacc[j][2] - mn1);
            const float e3 = __expf(sacc[j][3] - mn1);
            s0 += e0 + e1;
            s1 += e2 + e3;
            pf[j][0] = packh2(e0, e1);
            pf[j][1] = packh2(e2, e3);
        }
        s0 += __shfl_xor_sync(0xffffffffu, s0, 1);
        s0 += __shfl_xor_sync(0xffffffffu, s0, 2);
        s1 += __shfl_xor_sync(0xffffffffu, s1, 1);
        s1 += __shfl_xor_sync(0xffffffffu, s1, 2);
        lrow[0] = lrow[0] * sc0 + s0;
        lrow[1] = lrow[1] * sc1 + s1;
#pragma unroll
        for (int j = 0; j < 16; j++) {
            o[j][0] *= sc0; o[j][1] *= sc0;
            o[j][2] *= sc1; o[j][3] *= sc1;
        }

        // ---- O += P @ V ----
#pragma unroll
        for (int kc = 0; kc < 8; kc++) {
            const int sec = kc >> 1;
            const int c   = (kc & 1) * 2 + kaddp;
            uint4 a;
            a.x = pf[kc * 2][0];
            a.y = pf[kc * 2][1];
            a.z = pf[kc * 2 + 1][0];
            a.w = pf[kc * 2 + 1][1];
#pragma unroll
            for (int np = 0; np < 8; np++) {
                const int row = np * 16 + rB0;
                const int sw  = c ^ ((row >> 1) & 3);
                uint4 bq;
                ldmx4(bq, vb + sec * 8192 + row * 64 + sw * 16);
                MMA16816(o[np * 2],     a, bq.x, bq.z);
                MMA16816(o[np * 2 + 1], a, bq.y, bq.w);
            }
        }

        __syncthreads();

        // issue KV block jb+2 into buffer jb&1 (after all reads done)
        const int nb = jb + 2;
        if (nb < NBLK) {
            const uint32_t nkb = sbase + FA_QSM + (nb & 1) * FA_KV;
#pragma unroll
            for (int sec = 0; sec < 4; sec++)
#pragma unroll
                for (int j = 0; j < 2; j++) {
                    cp16(nkb + sec * 8192 + soff[j],
                         Kp + (size_t)(nb * 128 + rr[j]) * DMODEL + sec * 32 + kc8[j]);
                    cp16(nkb + 32768 + sec * 8192 + soff[j],
                         Vp + (size_t)rr[j] * S_TOT + nb * 128 + sec * 32 + kc8[j]);
                }
        }
        asm volatile("cp.async.commit_group;");
    }

    // ---- finalize: O / l, write fp16 ----
    const float inv0 = 1.0f / lrow[0];
    const float inv1 = 1.0f / lrow[1];
    __half* Op = Og + (size_t)(qb * 128) * DMODEL + h * DH;
#pragma unroll
    for (int j = 0; j < 16; j++) {
        const int col  = j * 8 + tg * 2;
        const int row0 = wid * 16 + g;
        *(uint32_t*)(Op + (size_t)row0 * DMODEL + col) =
            packh2(o[j][0] * inv0, o[j][1] * inv0);
        *(uint32_t*)(Op + (size_t)(row0 + 8) * DMODEL + col) =
            packh2(o[j][2] * inv1, o[j][3] * inv1);
    }
}

// ---------------------------------------------------------------------------
// float -> half elementwise
// ---------------------------------------------------------------------------
__global__ __launch_bounds__(256)
void f2h_kernel(const float* __restrict__ in, __half* __restrict__ out)
{
    const size_t i = ((size_t)blockIdx.x * 256 + threadIdx.x) * 4;
    float4 v = *(const float4*)(in + i);
    *(uint2*)(out + i) = make_uint2(packh2(v.x, v.y), packh2(v.z, v.w));
}

// ---------------------------------------------------------------------------
// Tiled transpose fp32 -> fp16
// ---------------------------------------------------------------------------
__global__ __launch_bounds__(256)
void transpose_h(const float* __restrict__ in, __half* __restrict__ out, int R, int C)
{
    __shared__ float t[32][33];
    const int bx = blockIdx.x * 32;
    const int by = blockIdx.y * 32;
    const int tx = threadIdx.x & 31;
    const int ty = threadIdx.x >> 5;
#pragma unroll
    for (int j = 0; j < 32; j += 8)
        t[ty + j][tx] = in[(size_t)(by + ty + j) * C + bx + tx];
    __syncthreads();
#pragma unroll
    for (int j = 0; j < 32; j += 8)
        out[(size_t)(bx + ty + j) * R + by + tx] = __float2half(t[tx][ty + j]);
}

// ---------------------------------------------------------------------------
// Fused RMSNorm + RoPE -> fp16 q (scaled), k, and V^T
// ---------------------------------------------------------------------------
__device__ __forceinline__ float warp_sum(float v) {
#pragma unroll
    for (int o = 16; o > 0; o >>= 1) v += __shfl_xor_sync(0xffffffffu, v, o);
    return v;
}

__global__ __launch_bounds__(128)
void fuse_norm_rope(const float* __restrict__ qkv, const float* __restrict__ eqkv,
                    const int* __restrict__ ids,
                    const float* __restrict__ nq_w,  const float* __restrict__ nk_w,
                    const float* __restrict__ naq_w, const float* __restrict__ nak_w,
                    __half* __restrict__ Q, __half* __restrict__ Ko,
                    __half* __restrict__ VT)
{
    const int s = blockIdx.x;
    const int h = blockIdx.y;
    const int d = threadIdx.x;

    const float* src;
    const float* qw;
    const float* kw;
    if (s < S_TXT) { src = eqkv + (size_t)s * D3;           qw = naq_w; kw = nak_w; }
    else           { src = qkv  + (size_t)(s - S_TXT) * D3; qw = nq_w;  kw = nk_w; }

    float qv = src[h * DH + d];
    float kv = src[DMODEL   + h * DH + d];
    float vv = src[2*DMODEL + h * DH + d];

    __shared__ float sq[4], sk[4];
    float wq = warp_sum(qv * qv);
    float wk = warp_sum(kv * kv);
    const int w = d >> 5;
    if ((d & 31) == 0) { sq[w] = wq; sk[w] = wk; }
    __syncthreads();
    float qsum = sq[0] + sq[1] + sq[2] + sq[3];
    float ksum = sk[0] + sk[1] + sk[2] + sk[3];
    float qn = qv * rsqrtf(qsum * (1.0f / DH) + 1e-5f) * qw[d];
    float kn = kv * rsqrtf(ksum * (1.0f / DH) + 1e-5f) * kw[d];

    const int pr = d >> 1;
    int axis, base, dax;
    if      (pr < 8)  { axis = 0; base = 0;  dax = 16; }
    else if (pr < 36) { axis = 1; base = 8;  dax = 56; }
    else              { axis = 2; base = 36; dax = 56; }
    float e    = (2.0f * (float)(pr - base)) / (float)dax;
    float freq = expf(-e * 9.210340371976184f);
    float pos  = (float)ids[s * 3 + axis];
    float ang  = pos * freq;
    float cs, sn;
    sincosf(ang, &sn, &cs);

    float q_other = __shfl_xor_sync(0xffffffffu, qn, 1);
    float k_other = __shfl_xor_sync(0xffffffffu, kn, 1);
    float qr, kr;
    if (d & 1) { qr = qn * cs + q_other * sn; kr = kn * cs + k_other * sn; }
    else       { qr = qn * cs - q_other * sn; kr = kn * cs - k_other * sn; }

    const size_t o = (size_t)s * DMODEL + h * DH + d;
    Q[o]  = __float2half(qr * 0.08838834764831845f);
    Ko[o] = __float2half(kr);
    VT[(size_t)(h * DH + d) * S_TOT + s] = __float2half(vv);
}

// ---------------------------------------------------------------------------
// kernel_launch
// ---------------------------------------------------------------------------
extern "C" void kernel_launch(void* const* d_in, const int* in_sizes, int n_in,
                              void* d_out, int out_size)
{
    const float* hidden     = (const float*)d_in[0];
    const float* enc        = (const float*)d_in[1];
    const int*   ids        = (const int*)  d_in[2];
    const float* w_qkv      = (const float*)d_in[3];
    const float* w_add_qkv  = (const float*)d_in[4];
    const float* b_add_qkv  = (const float*)d_in[5];
    const float* w_out      = (const float*)d_in[6];
    const float* b_out      = (const float*)d_in[7];
    const float* w_add_out  = (const float*)d_in[8];
    const float* b_add_out  = (const float*)d_in[9];
    const float* norm_q_w   = (const float*)d_in[10];
    const float* norm_k_w   = (const float*)d_in[11];
    const float* norm_aq_w  = (const float*)d_in[12];
    const float* norm_ak_w  = (const float*)d_in[13];
    float* out = (float*)d_out;

    float *qkv, *eqkv;
    __half *hh, *eh, *qh, *kh, *vt, *attnh, *wtq, *wtaq, *wto, *wtao;
    cudaGetSymbolAddress((void**)&qkv,   g_qkv);
    cudaGetSymbolAddress((void**)&eqkv,  g_eqkv);
    cudaGetSymbolAddress((void**)&hh,    g_hh);
    cudaGetSymbolAddress((void**)&eh,    g_eh);
    cudaGetSymbolAddress((void**)&qh,    g_qh);
    cudaGetSymbolAddress((void**)&kh,    g_kh);
    cudaGetSymbolAddress((void**)&vt,    g_vt);
    cudaGetSymbolAddress((void**)&attnh, g_attnh);
    cudaGetSymbolAddress((void**)&wtq,   g_wtq);
    cudaGetSymbolAddress((void**)&wtaq,  g_wtaq);
    cudaGetSymbolAddress((void**)&wto,   g_wto);
    cudaGetSymbolAddress((void**)&wtao,  g_wtao);

    cudaFuncSetAttribute(gemm_nt_h, cudaFuncAttributeMaxDynamicSharedMemorySize,
                         GEMM_SMEM_BYTES);
    cudaFuncSetAttribute(flash_attn, cudaFuncAttributeMaxDynamicSharedMemorySize,
                         FA_SMEM);

    // 0) convert activations, transpose+convert weights (fp16 K-major)
    f2h_kernel<<<(S_IMG * DMODEL) / 1024, 256>>>(hidden, hh);
    f2h_kernel<<<(S_TXT * DMODEL) / 1024, 256>>>(enc, eh);
    transpose_h<<<dim3(D3/32, DMODEL/32), 256>>>(w_qkv,     wtq,  DMODEL, D3);
    transpose_h<<<dim3(D3/32, DMODEL/32), 256>>>(w_add_qkv, wtaq, DMODEL, D3);
    transpose_h<<<dim3(DMODEL/32, DMODEL/32), 256>>>(w_out,     wto,  DMODEL, DMODEL);
    transpose_h<<<dim3(DMODEL/32, DMODEL/32), 256>>>(w_add_out, wtao, DMODEL, DMODEL);

    // 1) qkv = hidden @ w_qkv            (fp32 out)
    gemm_nt_h<<<dim3(D3/128, S_IMG/128, 1), 256, GEMM_SMEM_BYTES>>>(
        hh, wtq, nullptr, qkv, DMODEL, DMODEL, DMODEL, D3, 0, 0, 0, 0);

    // 2) eqkv = enc @ w_add_qkv + b      (fp32 out)
    gemm_nt_h<<<dim3(D3/128, S_TXT/128, 1), 256, GEMM_SMEM_BYTES>>>(
        eh, wtaq, b_add_qkv, eqkv, DMODEL, DMODEL, DMODEL, D3, 0, 0, 0, 0);

    // 3) RMSNorm + RoPE -> fp16 q,k and fp16 V^T
    fuse_norm_rope<<<dim3(S_TOT, NHEADS), 128>>>(
        qkv, eqkv, ids, norm_q_w, norm_k_w, norm_aq_w, norm_ak_w, qh, kh, vt);

    // 4) fused attention -> attnh fp16 [S, 3072]
    flash_attn<<<dim3(S_TOT/128, NHEADS), 256, FA_SMEM>>>(qh, kh, vt, attnh);

    // 5) img_out = attn[512:] @ w_out + b_out
    gemm_nt_h<<<dim3(DMODEL/128, S_IMG/128, 1), 256, GEMM_SMEM_BYTES>>>(
        attnh + (size_t)S_TXT * DMODEL, wto, b_out, out,
        DMODEL, DMODEL, DMODEL, DMODEL, 0, 0, 0, 0);

    // 6) enc_out = attn[:512] @ w_add_out + b_add_out
    gemm_nt_h<<<dim3(DMODEL/128, S_TXT/128, 1), 256, GEMM_SMEM_BYTES>>>(
        attnh, wtao, b_add_out, out + (size_t)S_IMG * DMODEL,
        DMODEL, DMODEL, DMODEL, DMODEL, 0, 0, 0, 0);
}

// round 8
// speedup vs baseline: 2.7104x; 1.0133x over previous
#include <cuda_runtime.h>
#include <cuda_fp16.h>
#include <cstdint>
#include <math.h>

// ---------------------------------------------------------------------------
// Problem constants (Flux dual-stream attention block)
// ---------------------------------------------------------------------------
#define S_TXT   512
#define S_IMG   2048
#define S_TOT   2560
#define DMODEL  3072
#define NHEADS  24
#define DH      128
#define D3      9216

// ---------------------------------------------------------------------------
// Scratch (device globals -- allocation is forbidden)
// ---------------------------------------------------------------------------
__device__ float g_qkv [(size_t)S_IMG * D3];
__device__ float g_eqkv[(size_t)S_TXT * D3];

__device__ __align__(256) __half g_hh   [(size_t)S_IMG * DMODEL];
__device__ __align__(256) __half g_eh   [(size_t)S_TXT * DMODEL];
__device__ __align__(256) __half g_qh   [(size_t)S_TOT * DMODEL];
__device__ __align__(256) __half g_kh   [(size_t)S_TOT * DMODEL];
__device__ __align__(256) __half g_vt   [(size_t)DMODEL * S_TOT];
__device__ __align__(256) __half g_attnh[(size_t)S_TOT * DMODEL];
__device__ __align__(256) __half g_wtq  [(size_t)D3 * DMODEL];
__device__ __align__(256) __half g_wtaq [(size_t)D3 * DMODEL];
__device__ __align__(256) __half g_wto  [(size_t)DMODEL * DMODEL];
__device__ __align__(256) __half g_wtao [(size_t)DMODEL * DMODEL];

// ---------------------------------------------------------------------------
// helpers
// ---------------------------------------------------------------------------
__device__ __forceinline__ uint32_t smem_u32(const void* p) {
    uint32_t a;
    asm("{ .reg .u64 t; cvta.to.shared.u64 t, %1; cvt.u32.u64 %0, t; }" : "=r"(a) : "l"(p));
    return a;
}
__device__ __forceinline__ uint32_t packh2(float lo, float hi) {
    uint32_t r;
    asm("cvt.rn.f16x2.f32 %0, %1, %2;" : "=r"(r) : "f"(hi), "f"(lo));
    return r;
}
__device__ __forceinline__ uint32_t ex2h2(uint32_t x) {
    uint32_t r;
    asm("ex2.approx.f16x2 %0, %1;" : "=r"(r) : "r"(x));
    return r;
}
__device__ __forceinline__ void cp16(uint32_t saddr, const void* gptr) {
    asm volatile("cp.async.cg.shared.global [%0], [%1], 16;" :: "r"(saddr), "l"(gptr));
}
__device__ __forceinline__ void ldmx4(uint4& f, uint32_t addr) {
    asm volatile("ldmatrix.sync.aligned.m8n8.x4.shared.b16 {%0,%1,%2,%3}, [%4];"
                 : "=r"(f.x), "=r"(f.y), "=r"(f.z), "=r"(f.w) : "r"(addr));
}
#define MMA16816(acc, a, b0, b1)                                               \
    asm volatile("mma.sync.aligned.m16n8k16.row.col.f32.f16.f16.f32 "          \
                 "{%0,%1,%2,%3}, {%4,%5,%6,%7}, {%8,%9}, {%0,%1,%2,%3};"       \
                 : "+f"((acc)[0]), "+f"((acc)[1]), "+f"((acc)[2]), "+f"((acc)[3]) \
                 : "r"((a).x), "r"((a).y), "r"((a).z), "r"((a).w),             \
                   "r"(b0), "r"(b1))

// ---------------------------------------------------------------------------
// fp16 cp.async-pipelined NT GEMM (proven from R6)
// ---------------------------------------------------------------------------
#define STAGE_BYTES 16384
#define GEMM_SMEM_BYTES (4 * STAGE_BYTES)

__global__ __launch_bounds__(256)
void gemm_nt_h(const __half* __restrict__ A, const __half* __restrict__ B,
               const float* __restrict__ bias, void* __restrict__ Cv,
               int K, int lda, int ldb, int ldc,
               long long sA, long long sB, long long sC, int out_half)
{
    extern __shared__ char smem[];
    const uint32_t sbase = smem_u32(smem);
    const int tid    = threadIdx.x;
    const int lane   = tid & 31;
    const int wid    = tid >> 5;
    const int warp_m = wid >> 2;
    const int warp_n = wid & 3;
    const int bm     = blockIdx.y * 128;
    const int bn     = blockIdx.x * 128;

    A += (size_t)blockIdx.z * sA + (size_t)bm * lda;
    B += (size_t)blockIdx.z * sB + (size_t)bn * ldb;

    uint32_t soff[2];
    size_t   goa[2], gob[2];
#pragma unroll
    for (int j = 0; j < 2; j++) {
        const int c  = tid + j * 256;
        const int r  = c >> 2;
        const int kc = c & 3;
        const int sw = kc ^ ((r >> 1) & 3);
        soff[j] = (uint32_t)(r * 64 + sw * 16);
        goa[j]  = (size_t)r * lda + kc * 8;
        gob[j]  = (size_t)r * ldb + kc * 8;
    }

    const int T = K >> 5;

#pragma unroll
    for (int s = 0; s < 3; s++) {
        const uint32_t sa = sbase + s * STAGE_BYTES;
        if (s < T) {
#pragma unroll
            for (int j = 0; j < 2; j++) {
                cp16(sa + soff[j],        A + goa[j] + s * 32);
                cp16(sa + 8192 + soff[j], B + gob[j] + s * 32);
            }
        }
        asm volatile("cp.async.commit_group;");
    }

    float acc[4][4][4];
#pragma unroll
    for (int m = 0; m < 4; m++)
#pragma unroll
        for (int n = 0; n < 4; n++)
#pragma unroll
            for (int x = 0; x < 4; x++) acc[m][n][x] = 0.0f;

    const int p    = lane >> 3;
    const int li   = lane & 7;
    const int rA0  = warp_m * 64 + (p & 1) * 8 + li;
    const int rB0  = warp_n * 32 + (p & 1) * 8 + li;
    const int kaddp = p >> 1;

    for (int t = 0; t < T; t++) {
        asm volatile("cp.async.wait_group 2;");
        __syncthreads();
        {
            const int kt = t + 3;
            const uint32_t sa = sbase + (kt & 3) * STAGE_BYTES;
            if (kt < T) {
#pragma unroll
                for (int j = 0; j < 2; j++) {
                    cp16(sa + soff[j],        A + goa[j] + (size_t)kt * 32);
                    cp16(sa + 8192 + soff[j], B + gob[j] + (size_t)kt * 32);
                }
            }
            asm volatile("cp.async.commit_group;");
        }

        const uint32_t st = sbase + (t & 3) * STAGE_BYTES;
#pragma unroll
        for (int ks = 0; ks < 2; ks++) {
            const int kc = ks * 2 + kaddp;
            uint4 af[4];
#pragma unroll
            for (int mt = 0; mt < 4; mt++) {
                const int row = rA0 + mt * 16;
                const int sw  = kc ^ ((row >> 1) & 3);
                ldmx4(af[mt], st + row * 64 + sw * 16);
            }
            uint4 bq[2];
#pragma unroll
            for (int ntp = 0; ntp < 2; ntp++) {
                const int row = rB0 + ntp * 16;
                const int sw  = kc ^ ((row >> 1) & 3);
                ldmx4(bq[ntp], st + 8192 + row * 64 + sw * 16);
            }
            uint2 bf[4];
            bf[0] = make_uint2(bq[0].x, bq[0].z);
            bf[1] = make_uint2(bq[0].y, bq[0].w);
            bf[2] = make_uint2(bq[1].x, bq[1].z);
            bf[3] = make_uint2(bq[1].y, bq[1].w);
#pragma unroll
            for (int m = 0; m < 4; m++)
#pragma unroll
                for (int n = 0; n < 4; n++)
                    MMA16816(acc[m][n], af[m], bf[n].x, bf[n].y);
        }
        __syncthreads();
    }

    const int g  = lane >> 2;
    const int tg = lane & 3;
    if (out_half) {
        __half* C = (__half*)Cv + (size_t)blockIdx.z * sC;
#pragma unroll
        for (int m = 0; m < 4; m++) {
            const int row0 = bm + warp_m * 64 + m * 16 + g;
#pragma unroll
            for (int n = 0; n < 4; n++) {
                const int col = bn + warp_n * 32 + n * 8 + tg * 2;
                *(uint32_t*)(C + (size_t)row0 * ldc + col) =
                    packh2(acc[m][n][0], acc[m][n][1]);
                *(uint32_t*)(C + (size_t)(row0 + 8) * ldc + col) =
                    packh2(acc[m][n][2], acc[m][n][3]);
            }
        }
    } else {
        float* C = (float*)Cv + (size_t)blockIdx.z * sC;
#pragma unroll
        for (int m = 0; m < 4; m++) {
            const int row0 = bm + warp_m * 64 + m * 16 + g;
#pragma unroll
            for (int n = 0; n < 4; n++) {
                const int col = bn + warp_n * 32 + n * 8 + tg * 2;
                float bx = 0.f, by = 0.f;
                if (bias) { bx = bias[col]; by = bias[col + 1]; }
                *(float2*)(C + (size_t)row0 * ldc + col) =
                    make_float2(acc[m][n][0] + bx, acc[m][n][1] + by);
                *(float2*)(C + (size_t)(row0 + 8) * ldc + col) =
                    make_float2(acc[m][n][2] + bx, acc[m][n][3] + by);
            }
        }
    }
}

// ---------------------------------------------------------------------------
// Fused flash attention, log2-domain softmax, mma-computed row sums.
// CTA = (q-block 128, head), 256 thr = 8 warps, warp = 16 q-rows.
// smem: Q 32KB | 2 x (K 32KB + V 36KB(144 rows: 128 dh + ones + zeros pad)).
// V row 128 = 1.0 -> O column 128 accumulates the rescaled softmax denom.
// ---------------------------------------------------------------------------
#define FA_QSM    32768
#define FA_KBYTES 32768
#define FA_VSEC   9216          // 144 rows x 64 B
#define FA_VBYTES (4 * FA_VSEC) // 36864
#define FA_KV     (FA_KBYTES + FA_VBYTES)
#define FA_SMEM   (FA_QSM + 2 * FA_KV)   // 172032
#define NBLK      (S_TOT / 128)          // 20

__global__ __launch_bounds__(256)
void flash_attn(const __half* __restrict__ Qg, const __half* __restrict__ Kg,
                const __half* __restrict__ VTg, __half* __restrict__ Og)
{
    extern __shared__ char smem[];
    const uint32_t sbase = smem_u32(smem);
    const int tid  = threadIdx.x;
    const int lane = tid & 31;
    const int wid  = tid >> 5;
    const int qb   = blockIdx.x;
    const int h    = blockIdx.y;

    uint32_t soff[2];
    int rr[2], kc8[2];
#pragma unroll
    for (int j = 0; j < 2; j++) {
        const int c  = tid + j * 256;
        const int r  = c >> 2;
        const int kc = c & 3;
        soff[j] = (uint32_t)(r * 64 + (kc ^ ((r >> 1) & 3)) * 16);
        rr[j]   = r;
        kc8[j]  = kc * 8;
    }

    const __half* Qp = Qg + (size_t)(qb * 128) * DMODEL + h * DH;
    const __half* Kp = Kg + h * DH;
    const __half* Vp = VTg + (size_t)(h * DH) * S_TOT;

    // init V pad rows (128 = ones, 129..143 = zeros) in both buffers, all secs
#pragma unroll
    for (int bs = 0; bs < 8; bs++) {
        const int buf = bs >> 2;
        const int sec = bs & 3;
        const uint32_t base = sbase + FA_QSM + buf * FA_KV + FA_KBYTES
                            + sec * FA_VSEC + 128 * 64;
        // 16 rows x 16 words = 256 words; 256 threads -> 1 word each
        const int w = tid;
        *(uint32_t*)(smem + (base - sbase) + w * 4) = (w < 16) ? 0x3C003C00u : 0u;
    }

    // issue Q (4 sections) + KV block 0 -> group 0
#pragma unroll
    for (int sec = 0; sec < 4; sec++)
#pragma unroll
        for (int j = 0; j < 2; j++)
            cp16(sbase + sec * 8192 + soff[j],
                 Qp + (size_t)rr[j] * DMODEL + sec * 32 + kc8[j]);
    {
        const uint32_t kb = sbase + FA_QSM;
        const uint32_t vb = kb + FA_KBYTES;
#pragma unroll
        for (int sec = 0; sec < 4; sec++)
#pragma unroll
            for (int j = 0; j < 2; j++) {
                cp16(kb + sec * 8192 + soff[j],
                     Kp + (size_t)rr[j] * DMODEL + sec * 32 + kc8[j]);
                cp16(vb + sec * FA_VSEC + soff[j],
                     Vp + (size_t)rr[j] * S_TOT + sec * 32 + kc8[j]);
            }
    }
    asm volatile("cp.async.commit_group;");
    // KV block 1 -> group 1
    {
        const uint32_t kb = sbase + FA_QSM + FA_KV;
        const uint32_t vb = kb + FA_KBYTES;
#pragma unroll
        for (int sec = 0; sec < 4; sec++)
#pragma unroll
            for (int j = 0; j < 2; j++) {
                cp16(kb + sec * 8192 + soff[j],
                     Kp + (size_t)(128 + rr[j]) * DMODEL + sec * 32 + kc8[j]);
                cp16(vb + sec * FA_VSEC + soff[j],
                     Vp + (size_t)rr[j] * S_TOT + 128 + sec * 32 + kc8[j]);
            }
    }
    asm volatile("cp.async.commit_group;");

    const int p     = lane >> 3;
    const int li    = lane & 7;
    const int kaddp = p >> 1;
    const int rowQ  = wid * 16 + (p & 1) * 8 + li;
    const int rB0   = (p & 1) * 8 + li;
    const int g     = lane >> 2;
    const int tg    = lane & 3;

    float mrow[2] = {-1e30f, -1e30f};
    float o[18][4];
#pragma unroll
    for (int j = 0; j < 18; j++)
#pragma unroll
        for (int x = 0; x < 4; x++) o[j][x] = 0.f;
    uint4 qf[8];

    for (int jb = 0; jb < NBLK; jb++) {
        asm volatile("cp.async.wait_group 1;");
        __syncthreads();

        if (jb == 0) {
#pragma unroll
            for (int kc = 0; kc < 8; kc++) {
                const int sec = kc >> 1;
                const int c   = (kc & 1) * 2 + kaddp;
                const int sw  = c ^ ((rowQ >> 1) & 3);
                ldmx4(qf[kc], sbase + sec * 8192 + rowQ * 64 + sw * 16);
            }
        }

        const uint32_t kb = sbase + FA_QSM + (jb & 1) * FA_KV;
        const uint32_t vb = kb + FA_KBYTES;

        // ---- S' = (log2e-scaled Q) @ K^T ----
        float sacc[16][4];
#pragma unroll
        for (int j = 0; j < 16; j++)
#pragma unroll
            for (int x = 0; x < 4; x++) sacc[j][x] = 0.f;
#pragma unroll
        for (int kc = 0; kc < 8; kc++) {
            const int sec = kc >> 1;
            const int c   = (kc & 1) * 2 + kaddp;
#pragma unroll
            for (int np = 0; np < 8; np++) {
                const int row = np * 16 + rB0;
                const int sw  = c ^ ((row >> 1) & 3);
                uint4 bq;
                ldmx4(bq, kb + sec * 8192 + row * 64 + sw * 16);
                MMA16816(sacc[np * 2],     qf[kc], bq.x, bq.z);
                MMA16816(sacc[np * 2 + 1], qf[kc], bq.y, bq.w);
            }
        }

        // ---- online softmax (log2 domain; p via dual-fp16 ex2) ----
        float mx0 = -1e30f, mx1 = -1e30f;
#pragma unroll
        for (int j = 0; j < 16; j++) {
            mx0 = fmaxf(mx0, fmaxf(sacc[j][0], sacc[j][1]));
            mx1 = fmaxf(mx1, fmaxf(sacc[j][2], sacc[j][3]));
        }
        mx0 = fmaxf(mx0, __shfl_xor_sync(0xffffffffu, mx0, 1));
        mx0 = fmaxf(mx0, __shfl_xor_sync(0xffffffffu, mx0, 2));
        mx1 = fmaxf(mx1, __shfl_xor_sync(0xffffffffu, mx1, 1));
        mx1 = fmaxf(mx1, __shfl_xor_sync(0xffffffffu, mx1, 2));

        const float mn0 = fmaxf(mrow[0], mx0);
        const float mn1 = fmaxf(mrow[1], mx1);
        const float sc0 = exp2f(mrow[0] - mn0);
        const float sc1 = exp2f(mrow[1] - mn1);
        mrow[0] = mn0; mrow[1] = mn1;

        uint32_t pf[16][2];
#pragma unroll
        for (int j = 0; j < 16; j++) {
            pf[j][0] = ex2h2(packh2(sacc[j][0] - mn0, sacc[j][1] - mn0));
            pf[j][1] = ex2h2(packh2(sacc[j][2] - mn1, sacc[j][3] - mn1));
        }
#pragma unroll
        for (int j = 0; j < 18; j++) {
            o[j][0] *= sc0; o[j][1] *= sc0;
            o[j][2] *= sc1; o[j][3] *= sc1;
        }

        // ---- O += P @ V  (np=8 tile carries the ones-row -> row sums) ----
#pragma unroll
        for (int kc = 0; kc < 8; kc++) {
            const int sec = kc >> 1;
            const int c   = (kc & 1) * 2 + kaddp;
            uint4 a;
            a.x = pf[kc * 2][0];
            a.y = pf[kc * 2][1];
            a.z = pf[kc * 2 + 1][0];
            a.w = pf[kc * 2 + 1][1];
#pragma unroll
            for (int np = 0; np < 9; np++) {
                const int row = np * 16 + rB0;
                const int sw  = c ^ ((row >> 1) & 3);
                uint4 bq;
                ldmx4(bq, vb + sec * FA_VSEC + row * 64 + sw * 16);
                MMA16816(o[np * 2],     a, bq.x, bq.z);
                MMA16816(o[np * 2 + 1], a, bq.y, bq.w);
            }
        }

        __syncthreads();

        const int nb = jb + 2;
        if (nb < NBLK) {
            const uint32_t nkb = sbase + FA_QSM + (nb & 1) * FA_KV;
            const uint32_t nvb = nkb + FA_KBYTES;
#pragma unroll
            for (int sec = 0; sec < 4; sec++)
#pragma unroll
                for (int j = 0; j < 2; j++) {
                    cp16(nkb + sec * 8192 + soff[j],
                         Kp + (size_t)(nb * 128 + rr[j]) * DMODEL + sec * 32 + kc8[j]);
                    cp16(nvb + sec * FA_VSEC + soff[j],
                         Vp + (size_t)rr[j] * S_TOT + nb * 128 + sec * 32 + kc8[j]);
                }
        }
        asm volatile("cp.async.commit_group;");
    }

    // ---- finalize: l = O[:,128] (from ones-row), broadcast, divide, store ----
    const float l0 = __shfl_sync(0xffffffffu, o[16][0], lane & 28);
    const float l1 = __shfl_sync(0xffffffffu, o[16][2], lane & 28);
    const float inv0 = 1.0f / l0;
    const float inv1 = 1.0f / l1;
    __half* Op = Og + (size_t)(qb * 128) * DMODEL + h * DH;
#pragma unroll
    for (int j = 0; j < 16; j++) {
        const int col  = j * 8 + tg * 2;
        const int row0 = wid * 16 + g;
        *(uint32_t*)(Op + (size_t)row0 * DMODEL + col) =
            packh2(o[j][0] * inv0, o[j][1] * inv0);
        *(uint32_t*)(Op + (size_t)(row0 + 8) * DMODEL + col) =
            packh2(o[j][2] * inv1, o[j][3] * inv1);
    }
}

// ---------------------------------------------------------------------------
// float -> half elementwise
// ---------------------------------------------------------------------------
__global__ __launch_bounds__(256)
void f2h_kernel(const float* __restrict__ in, __half* __restrict__ out)
{
    const size_t i = ((size_t)blockIdx.x * 256 + threadIdx.x) * 4;
    float4 v = *(const float4*)(in + i);
    *(uint2*)(out + i) = make_uint2(packh2(v.x, v.y), packh2(v.z, v.w));
}

// ---------------------------------------------------------------------------
// Tiled transpose fp32 -> fp16
// ---------------------------------------------------------------------------
__global__ __launch_bounds__(256)
void transpose_h(const float* __restrict__ in, __half* __restrict__ out, int R, int C)
{
    __shared__ float t[32][33];
    const int bx = blockIdx.x * 32;
    const int by = blockIdx.y * 32;
    const int tx = threadIdx.x & 31;
    const int ty = threadIdx.x >> 5;
#pragma unroll
    for (int j = 0; j < 32; j += 8)
        t[ty + j][tx] = in[(size_t)(by + ty + j) * C + bx + tx];
    __syncthreads();
#pragma unroll
    for (int j = 0; j < 32; j += 8)
        out[(size_t)(bx + ty + j) * R + by + tx] = __float2half(t[tx][ty + j]);
}

// ---------------------------------------------------------------------------
// Fused RMSNorm + RoPE -> fp16 q (scale*log2e folded), k, V^T
// ---------------------------------------------------------------------------
__device__ __forceinline__ float warp_sum(float v) {
#pragma unroll
    for (int o = 16; o > 0; o >>= 1) v += __shfl_xor_sync(0xffffffffu, v, o);
    return v;
}

__global__ __launch_bounds__(128)
void fuse_norm_rope(const float* __restrict__ qkv, const float* __restrict__ eqkv,
                    const int* __restrict__ ids,
                    const float* __restrict__ nq_w,  const float* __restrict__ nk_w,
                    const float* __restrict__ naq_w, const float* __restrict__ nak_w,
                    __half* __restrict__ Q, __half* __restrict__ Ko,
                    __half* __restrict__ VT)
{
    const int s = blockIdx.x;
    const int h = blockIdx.y;
    const int d = threadIdx.x;

    const float* src;
    const float* qw;
    const float* kw;
    if (s < S_TXT) { src = eqkv + (size_t)s * D3;           qw = naq_w; kw = nak_w; }
    else           { src = qkv  + (size_t)(s - S_TXT) * D3; qw = nq_w;  kw = nk_w; }

    float qv = src[h * DH + d];
    float kv = src[DMODEL   + h * DH + d];
    float vv = src[2*DMODEL + h * DH + d];

    __shared__ float sq[4], sk[4];
    float wq = warp_sum(qv * qv);
    float wk = warp_sum(kv * kv);
    const int w = d >> 5;
    if ((d & 31) == 0) { sq[w] = wq; sk[w] = wk; }
    __syncthreads();
    float qsum = sq[0] + sq[1] + sq[2] + sq[3];
    float ksum = sk[0] + sk[1] + sk[2] + sk[3];
    float qn = qv * rsqrtf(qsum * (1.0f / DH) + 1e-5f) * qw[d];
    float kn = kv * rsqrtf(ksum * (1.0f / DH) + 1e-5f) * kw[d];

    const int pr = d >> 1;
    int axis, base, dax;
    if      (pr < 8)  { axis = 0; base = 0;  dax = 16; }
    else if (pr < 36) { axis = 1; base = 8;  dax = 56; }
    else              { axis = 2; base = 36; dax = 56; }
    float e    = (2.0f * (float)(pr - base)) / (float)dax;
    float freq = expf(-e * 9.210340371976184f);
    float pos  = (float)ids[s * 3 + axis];
    float ang  = pos * freq;
    float cs, sn;
    sincosf(ang, &sn, &cs);

    float q_other = __shfl_xor_sync(0xffffffffu, qn, 1);
    float k_other = __shfl_xor_sync(0xffffffffu, kn, 1);
    float qr, kr;
    if (d & 1) { qr = qn * cs + q_other * sn; kr = kn * cs + k_other * sn; }
    else       { qr = qn * cs - q_other * sn; kr = kn * cs - k_other * sn; }

    const size_t o = (size_t)s * DMODEL + h * DH + d;
    // fold 1/sqrt(Dh) * log2(e) so flash works in log2 domain
    Q[o]  = __float2half(qr * (0.08838834764831845f * 1.4426950408889634f));
    Ko[o] = __float2half(kr);
    VT[(size_t)(h * DH + d) * S_TOT + s] = __float2half(vv);
}

// ---------------------------------------------------------------------------
// kernel_launch
// ---------------------------------------------------------------------------
extern "C" void kernel_launch(void* const* d_in, const int* in_sizes, int n_in,
                              void* d_out, int out_size)
{
    const float* hidden     = (const float*)d_in[0];
    const float* enc        = (const float*)d_in[1];
    const int*   ids        = (const int*)  d_in[2];
    const float* w_qkv      = (const float*)d_in[3];
    const float* w_add_qkv  = (const float*)d_in[4];
    const float* b_add_qkv  = (const float*)d_in[5];
    const float* w_out      = (const float*)d_in[6];
    const float* b_out      = (const float*)d_in[7];
    const float* w_add_out  = (const float*)d_in[8];
    const float* b_add_out  = (const float*)d_in[9];
    const float* norm_q_w   = (const float*)d_in[10];
    const float* norm_k_w   = (const float*)d_in[11];
    const float* norm_aq_w  = (const float*)d_in[12];
    const float* norm_ak_w  = (const float*)d_in[13];
    float* out = (float*)d_out;

    float *qkv, *eqkv;
    __half *hh, *eh, *qh, *kh, *vt, *attnh, *wtq, *wtaq, *wto, *wtao;
    cudaGetSymbolAddress((void**)&qkv,   g_qkv);
    cudaGetSymbolAddress((void**)&eqkv,  g_eqkv);
    cudaGetSymbolAddress((void**)&hh,    g_hh);
    cudaGetSymbolAddress((void**)&eh,    g_eh);
    cudaGetSymbolAddress((void**)&qh,    g_qh);
    cudaGetSymbolAddress((void**)&kh,    g_kh);
    cudaGetSymbolAddress((void**)&vt,    g_vt);
    cudaGetSymbolAddress((void**)&attnh, g_attnh);
    cudaGetSymbolAddress((void**)&wtq,   g_wtq);
    cudaGetSymbolAddress((void**)&wtaq,  g_wtaq);
    cudaGetSymbolAddress((void**)&wto,   g_wto);
    cudaGetSymbolAddress((void**)&wtao,  g_wtao);

    cudaFuncSetAttribute(gemm_nt_h, cudaFuncAttributeMaxDynamicSharedMemorySize,
                         GEMM_SMEM_BYTES);
    cudaFuncSetAttribute(flash_attn, cudaFuncAttributeMaxDynamicSharedMemorySize,
                         FA_SMEM);

    // 0) convert activations, transpose+convert weights (fp16 K-major)
    f2h_kernel<<<(S_IMG * DMODEL) / 1024, 256>>>(hidden, hh);
    f2h_kernel<<<(S_TXT * DMODEL) / 1024, 256>>>(enc, eh);
    transpose_h<<<dim3(D3/32, DMODEL/32), 256>>>(w_qkv,     wtq,  DMODEL, D3);
    transpose_h<<<dim3(D3/32, DMODEL/32), 256>>>(w_add_qkv, wtaq, DMODEL, D3);
    transpose_h<<<dim3(DMODEL/32, DMODEL/32), 256>>>(w_out,     wto,  DMODEL, DMODEL);
    transpose_h<<<dim3(DMODEL/32, DMODEL/32), 256>>>(w_add_out, wtao, DMODEL, DMODEL);

    // 1) qkv = hidden @ w_qkv            (fp32 out)
    gemm_nt_h<<<dim3(D3/128, S_IMG/128, 1), 256, GEMM_SMEM_BYTES>>>(
        hh, wtq, nullptr, qkv, DMODEL, DMODEL, DMODEL, D3, 0, 0, 0, 0);

    // 2) eqkv = enc @ w_add_qkv + b      (fp32 out)
    gemm_nt_h<<<dim3(D3/128, S_TXT/128, 1), 256, GEMM_SMEM_BYTES>>>(
        eh, wtaq, b_add_qkv, eqkv, DMODEL, DMODEL, DMODEL, D3, 0, 0, 0, 0);

    // 3) RMSNorm + RoPE -> fp16 q,k and fp16 V^T
    fuse_norm_rope<<<dim3(S_TOT, NHEADS), 128>>>(
        qkv, eqkv, ids, norm_q_w, norm_k_w, norm_aq_w, norm_ak_w, qh, kh, vt);

    // 4) fused attention -> attnh fp16 [S, 3072]
    flash_attn<<<dim3(S_TOT/128, NHEADS), 256, FA_SMEM>>>(qh, kh, vt, attnh);

    // 5) img_out = attn[512:] @ w_out + b_out
    gemm_nt_h<<<dim3(DMODEL/128, S_IMG/128, 1), 256, GEMM_SMEM_BYTES>>>(
        attnh + (size_t)S_TXT * DMODEL, wto, b_out, out,
        DMODEL, DMODEL, DMODEL, DMODEL, 0, 0, 0, 0);

    // 6) enc_out = attn[:512] @ w_add_out + b_add_out
    gemm_nt_h<<<dim3(DMODEL/128, S_TXT/128, 1), 256, GEMM_SMEM_BYTES>>>(
        attnh, wtao, b_add_out, out + (size_t)S_IMG * DMODEL,
        DMODEL, DMODEL, DMODEL, DMODEL, 0, 0, 0, 0);
}